// round 8
// baseline (speedup 1.0000x reference)
#include <cuda_runtime.h>
#include <math.h>
#include <stdint.h>

#define BB 2
#define NH 8
#define DH 64
#define DM 512
#define NQ 4096
#define NKK 4096
#define MROWS (BB*NQ)                       // 8192
#define ATTN_ELEMS ((size_t)NH*BB*(size_t)NQ*(size_t)NKK)   // 268435456

// scratch (device globals; no allocation allowed)
__device__ float g_q[BB*NH*NQ*DH];   // d-permuted within 8-blocks
__device__ float g_k[BB*NH*NKK*DH];  // d-permuted within 8-blocks
__device__ float g_v[BB*NH*NKK*DH];  // TRANSPOSED per head: [bh][d][n]
__device__ float g_o[MROWS*DM];
__device__ float g_l[BB*NH*NQ];

// ===========================================================================
// helpers
// ===========================================================================
__device__ __forceinline__ uint32_t s2u(const void* p){
    uint32_t a;
    asm("{ .reg .u64 t; cvta.to.shared.u64 t, %1; cvt.u32.u64 %0, t; }"
        : "=r"(a) : "l"(p));
    return a;
}
__device__ __forceinline__ uint32_t f2tf(float f){
    uint32_t u; asm("cvt.rna.tf32.f32 %0, %1;" : "=r"(u) : "f"(f)); return u;
}
__device__ __forceinline__ float ex2f(float x){
    float y; asm("ex2.approx.ftz.f32 %0, %1;" : "=f"(y) : "f"(x)); return y;
}
__device__ __forceinline__ void mma8(float* d, const uint32_t* a,
                                     uint32_t b0, uint32_t b1){
    asm volatile("mma.sync.aligned.m16n8k8.row.col.f32.tf32.tf32.f32 "
        "{%0,%1,%2,%3}, {%4,%5,%6,%7}, {%8,%9}, {%0,%1,%2,%3};"
        : "+f"(d[0]), "+f"(d[1]), "+f"(d[2]), "+f"(d[3])
        : "r"(a[0]), "r"(a[1]), "r"(a[2]), "r"(a[3]), "r"(b0), "r"(b1));
}
__device__ __forceinline__ void cpa16(uint32_t s, const void* g){
    asm volatile("cp.async.cg.shared.global [%0], [%1], 16;" :: "r"(s), "l"(g));
}
#define CP_COMMIT() asm volatile("cp.async.commit_group;" ::: "memory")
#define CP_WAIT(n)  asm volatile("cp.async.wait_group %0;" :: "n"(n) : "memory")

// ===========================================================================
// Tensor-core NT GEMM with bias: C[M,512] = A[M,512] @ tf32(W[512,512])^T + b
// 2-term split: A = Ahi + Alo (tf32 each); C = Ahi*Whi + Alo*Whi  (= A*Whi)
// 128 threads / 4 warps (2m x 2n), CTA tile 64x64, k double-buffered.
// split=1: head-split [bh][n][d] with d permuted within 8-blocks
// split=2: head-split transposed [bh][d][n]
// split=0: plain row-major
// ===========================================================================
#define GP 68                    // smem pitch in floats (272B)
#define GTILEB (64*GP*4)         // 17408 B per tile buffer
#define GSM_BYTES (4*GTILEB)     // A0,A1,W0,W1

__global__ __launch_bounds__(128, 3) void gemm_tc(
    const float* __restrict__ A, const float* __restrict__ W,
    const float* __restrict__ bias, float* __restrict__ C, int split)
{
    extern __shared__ float sg[];
    uint32_t sb = s2u(sg);

    int tid = threadIdx.x;
    int w = tid >> 5, lane = tid & 31;
    int wm = w >> 1, wn = w & 1;
    int g = lane >> 2, t = lane & 3;

    int i0 = blockIdx.y * 64;
    int j0 = blockIdx.x * 64;

    const float* Ag = A + (size_t)i0 * DM;
    const float* Wg = W + (size_t)j0 * DM;

    // prologue: k-tile 0 (A rows + W rows)
    #pragma unroll
    for (int i = 0; i < 8; i++) {
        int c = tid + i * 128;             // 1024 chunks of 16B per tensor
        int r = c >> 4, c16 = c & 15;
        cpa16(sb + 0*GTILEB + (uint32_t)(r * GP + c16 * 4) * 4,
              Ag + (size_t)r * DM + c16 * 4);
        cpa16(sb + 2*GTILEB + (uint32_t)(r * GP + c16 * 4) * 4,
              Wg + (size_t)r * DM + c16 * 4);
    }
    CP_COMMIT();

    float acc[2][4][4] = {};

    for (int kt = 0; kt < 8; kt++) {
        int buf = kt & 1;
        CP_WAIT(0);
        __syncthreads();
        if (kt + 1 < 8) {
            int nb = buf ^ 1, k0n = (kt + 1) * 64;
            #pragma unroll
            for (int i = 0; i < 8; i++) {
                int c = tid + i * 128;
                int r = c >> 4, c16 = c & 15;
                cpa16(sb + nb*GTILEB + (uint32_t)(r * GP + c16 * 4) * 4,
                      Ag + (size_t)r * DM + k0n + c16 * 4);
                cpa16(sb + (2+nb)*GTILEB + (uint32_t)(r * GP + c16 * 4) * 4,
                      Wg + (size_t)r * DM + k0n + c16 * 4);
            }
            CP_COMMIT();
        }
        const float* As = sg + buf * (GTILEB/4);
        const float* Ws = sg + (2 + buf) * (GTILEB/4);

        #pragma unroll
        for (int s = 0; s < 8; s++) {
            uint32_t ah[2][4], al[2][4];
            #pragma unroll
            for (int mb = 0; mb < 2; mb++) {
                int R = wm * 32 + mb * 16 + g;
                float a0 = As[R * GP + s * 8 + t];
                float a1 = As[(R + 8) * GP + s * 8 + t];
                float a2 = As[R * GP + s * 8 + t + 4];
                float a3 = As[(R + 8) * GP + s * 8 + t + 4];
                ah[mb][0] = f2tf(a0); al[mb][0] = f2tf(a0 - __uint_as_float(ah[mb][0]));
                ah[mb][1] = f2tf(a1); al[mb][1] = f2tf(a1 - __uint_as_float(ah[mb][1]));
                ah[mb][2] = f2tf(a2); al[mb][2] = f2tf(a2 - __uint_as_float(ah[mb][2]));
                ah[mb][3] = f2tf(a3); al[mb][3] = f2tf(a3 - __uint_as_float(ah[mb][3]));
            }
            #pragma unroll
            for (int j = 0; j < 4; j++) {
                int n0 = wn * 32 + j * 8;
                uint32_t b0 = f2tf(Ws[(n0 + g) * GP + s * 8 + t]);
                uint32_t b1 = f2tf(Ws[(n0 + g) * GP + s * 8 + t + 4]);
                #pragma unroll
                for (int mb = 0; mb < 2; mb++) {
                    mma8(acc[mb][j], ah[mb], b0, b1);
                    mma8(acc[mb][j], al[mb], b0, b1);
                }
            }
        }
    }

    // ---- bias + split stores ----
    #pragma unroll
    for (int mb = 0; mb < 2; mb++) {
        int r = i0 + wm * 32 + mb * 16 + g;
        #pragma unroll
        for (int j = 0; j < 4; j++) {
            int n = j0 + wn * 32 + j * 8 + 2 * t;
            float bv0 = __ldg(bias + n), bv1 = __ldg(bias + n + 1);
            float c0 = acc[mb][j][0] + bv0, c1 = acc[mb][j][1] + bv1;
            float c2 = acc[mb][j][2] + bv0, c3 = acc[mb][j][3] + bv1;
            if (split == 0) {
                *(float2*)(C + (size_t)r * DM + n) = make_float2(c0, c1);
                *(float2*)(C + (size_t)(r + 8) * DM + n) = make_float2(c2, c3);
            } else if (split == 1) {
                int b = r >> 12, il = r & (NQ - 1);
                int h = n >> 6, dl = n & 63;
                int base = dl & ~7;
                int p0 = ((dl & 3) << 1) | ((dl >> 2) & 1);
                float* cb0 = C + (((size_t)(b * NH + h) * NQ + il) * DH + base);
                cb0[p0] = c0; cb0[p0 + 2] = c1;
                float* cb1 = cb0 + 8 * DH;
                cb1[p0] = c2; cb1[p0 + 2] = c3;
            } else {
                int b = r >> 12, il = r & (NQ - 1);
                int h = n >> 6, dl = n & 63;
                float* p = C + ((size_t)(b * NH + h) * DH + dl) * (size_t)NQ + il;
                p[0] = c0; p[(size_t)NQ] = c1;
                p[8] = c2; p[(size_t)NQ + 8] = c3;
            }
        }
    }
}

// ===========================================================================
// mma.sync tf32 attention. 128 threads / 4 warps (2m x 2n), 64 q-rows per
// CTA, 2 CTAs per SM. Warp tile 32q x 32n. Shuffle-free PV via
// k-permutation; LDS.64-paired fragments; P = ex2(S) with Q pre-scaled by
// 0.125*log2(e); unnormalized P streamed to gmem.  (unchanged from R7)
// ===========================================================================
#define PITCH 72                 // floats per smem row (288B)
#define TILEB (64*PITCH*4)       // 18432 B per tile buffer
#define KOFF(buf)  ((buf)*TILEB)
#define VOFF(buf)  (2*TILEB + (buf)*TILEB)
#define LSUM_F     (4*TILEB/4)           // float index
#define LINV_F     (LSUM_F + 128)
#define SM_BYTES   (4*TILEB + (128+64)*4)
#define NT         (NKK/64)              // 64 k-tiles
#define QSCALE     0.18033688f           // 0.125 * log2(e)
#define QROWS      64

__global__ __launch_bounds__(128, 2) void attn_mma(
    const unsigned char* __restrict__ mask, float* __restrict__ attn)
{
    extern __shared__ float smf[];
    uint32_t sb = s2u(smf);

    int tid  = threadIdx.x;
    int w    = tid >> 5, lane = tid & 31;
    int wm   = w >> 1,  wn = w & 1;
    int g    = lane >> 2, t = lane & 3;

    int bh = blockIdx.x;               // bh fastest -> K/V L2 sharing
    int b  = bh >> 3, h = bh & 7;
    int q0 = blockIdx.y * QROWS;

    const float* qg  = g_q + ((size_t)bh * NQ + q0) * DH;
    const float* kg  = g_k + (size_t)bh * NKK * DH;     // [n][d] (d permuted)
    const float* vtg = g_v + (size_t)bh * DH * NKK;     // [d][n]
    float* ab = attn + (size_t)(h * BB + b) * NQ * NKK;
    const unsigned char* mbase = mask + (size_t)b * NQ * NKK;

    // ---- stage Q (64 x 64) into smem, pre-scaled ----
    #pragma unroll
    for (int i = 0; i < 8; i++) {
        int idx = tid + i * 128;           // 1024 float4
        int r = idx >> 4, c4 = (idx & 15) << 2;
        float4 v = *(const float4*)(qg + (size_t)r * DH + c4);
        v.x *= QSCALE; v.y *= QSCALE; v.z *= QSCALE; v.w *= QSCALE;
        *(float4*)(smf + r * PITCH + c4) = v;
    }
    __syncthreads();

    // ---- preload Q A-fragments (tf32) via paired LDS.64 ----
    uint32_t qa[2][8][4];
    #pragma unroll
    for (int mb = 0; mb < 2; mb++) {
        int R = wm * 32 + mb * 16 + g;
        #pragma unroll
        for (int s = 0; s < 8; s++) {
            float2 lo = *(const float2*)(smf + R * PITCH + s * 8 + 2 * t);
            float2 hi = *(const float2*)(smf + (R + 8) * PITCH + s * 8 + 2 * t);
            qa[mb][s][0] = f2tf(lo.x);
            qa[mb][s][1] = f2tf(hi.x);
            qa[mb][s][2] = f2tf(lo.y);
            qa[mb][s][3] = f2tf(hi.y);
        }
    }
    __syncthreads();

    float oacc[2][8][4] = {};
    float lacc[2][2] = {};

    // ---- prologue: tile 0 (K rows + VT rows) ----
    #pragma unroll
    for (int i = 0; i < 8; i++) {
        int c = tid + i * 128;              // 1024 chunks of 16B per tensor
        int r = c >> 4, c16 = c & 15;
        cpa16(sb + KOFF(0) + (uint32_t)(r * PITCH + c16 * 4) * 4,
              kg + (size_t)r * DH + c16 * 4);
        cpa16(sb + VOFF(0) + (uint32_t)(r * PITCH + c16 * 4) * 4,
              vtg + (size_t)r * NKK + c16 * 4);
    }
    CP_COMMIT();

    for (int it = 0; it < NT; it++) {
        int buf = it & 1;
        CP_WAIT(0);
        __syncthreads();                    // data ready + prev buffer consumed
        if (it + 1 < NT) {
            int j0n = (it + 1) * 64, nb = buf ^ 1;
            #pragma unroll
            for (int i = 0; i < 8; i++) {
                int c = tid + i * 128;
                int r = c >> 4, c16 = c & 15;
                cpa16(sb + KOFF(nb) + (uint32_t)(r * PITCH + c16 * 4) * 4,
                      kg + (size_t)(j0n + r) * DH + c16 * 4);
                cpa16(sb + VOFF(nb) + (uint32_t)(r * PITCH + c16 * 4) * 4,
                      vtg + (size_t)r * NKK + j0n + c16 * 4);
            }
            CP_COMMIT();
        }

        const float* Ks = smf + KOFF(buf) / 4;
        const float* Vs = smf + VOFF(buf) / 4;   // [d-row][k-col]

        // ---- QK^T (paired B-frags: one LDS.64 each) ----
        float sacc[2][4][4] = {};
        #pragma unroll
        for (int s = 0; s < 8; s++) {
            #pragma unroll
            for (int j = 0; j < 4; j++) {
                int n0 = wn * 32 + j * 8;
                float2 kv = *(const float2*)(Ks + (n0 + g) * PITCH + s * 8 + 2 * t);
                uint32_t b0 = __float_as_uint(kv.x);
                uint32_t b1 = __float_as_uint(kv.y);
                mma8(sacc[0][j], qa[0][s], b0, b1);
                mma8(sacc[1][j], qa[1][s], b0, b1);
            }
        }

        // ---- epilogue + PV (shuffle-free, paired V B-frags) ----
        int jg0 = it * 64 + wn * 32;
        #pragma unroll
        for (int j = 0; j < 4; j++) {
            uint32_t pa[2][4];
            #pragma unroll
            for (int mb = 0; mb < 2; mb++) {
                int r0 = q0 + wm * 32 + mb * 16 + g;
                int colg = jg0 + j * 8 + 2 * t;
                const unsigned char* m0 = mbase + (size_t)r0 * NKK + colg;
                unsigned short mv0 = *(const unsigned short*)m0;
                unsigned short mv1 = *(const unsigned short*)(m0 + 8 * NKK);
                float* s4 = sacc[mb][j];
                float p0 = (mv0 & 0xff) ? 0.f : ex2f(s4[0]);
                float p1 = (mv0 >> 8)   ? 0.f : ex2f(s4[1]);
                float p2 = (mv1 & 0xff) ? 0.f : ex2f(s4[2]);
                float p3 = (mv1 >> 8)   ? 0.f : ex2f(s4[3]);
                lacc[mb][0] += p0 + p1;
                lacc[mb][1] += p2 + p3;
                __stcs((float2*)(ab + (size_t)r0 * NKK + colg), make_float2(p0, p1));
                __stcs((float2*)(ab + (size_t)(r0 + 8) * NKK + colg), make_float2(p2, p3));
                pa[mb][0] = f2tf(p0);
                pa[mb][1] = f2tf(p2);
                pa[mb][2] = f2tf(p1);
                pa[mb][3] = f2tf(p3);
            }
            int k0 = wn * 32 + j * 8;
            #pragma unroll
            for (int jd = 0; jd < 8; jd++) {
                float2 vv = *(const float2*)(Vs + (jd * 8 + g) * PITCH + k0 + 2 * t);
                uint32_t b0 = __float_as_uint(vv.x);
                uint32_t b1 = __float_as_uint(vv.y);
                mma8(oacc[0][jd], pa[0], b0, b1);
                mma8(oacc[1][jd], pa[1], b0, b1);
            }
        }
    }

    // ---- rowsum reduce ----
    #pragma unroll
    for (int off = 1; off <= 2; off <<= 1) {
        #pragma unroll
        for (int mb = 0; mb < 2; mb++) {
            lacc[mb][0] += __shfl_xor_sync(0xffffffffu, lacc[mb][0], off);
            lacc[mb][1] += __shfl_xor_sync(0xffffffffu, lacc[mb][1], off);
        }
    }
    float* lsum = smf + LSUM_F;
    float* linv = smf + LINV_F;
    __syncthreads();
    if (t == 0) {
        #pragma unroll
        for (int mb = 0; mb < 2; mb++) {
            lsum[wn * 64 + wm * 32 + mb * 16 + g]     = lacc[mb][0];
            lsum[wn * 64 + wm * 32 + mb * 16 + g + 8] = lacc[mb][1];
        }
    }
    __syncthreads();
    if (tid < QROWS) {
        float tot = lsum[tid] + lsum[64 + tid];
        g_l[(size_t)bh * NQ + q0 + tid] = tot;
        linv[tid] = 1.0f / tot;
    }
    __syncthreads();

    // ---- cross-warp(n) O reduction via smem (reuse KV region) ----
    if (wn == 1) {
        #pragma unroll
        for (int mb = 0; mb < 2; mb++) {
            int r = wm * 32 + mb * 16 + g;
            #pragma unroll
            for (int jd = 0; jd < 8; jd++) {
                *(float2*)(smf + r * PITCH + jd * 8 + 2 * t) =
                    make_float2(oacc[mb][jd][0], oacc[mb][jd][1]);
                *(float2*)(smf + (r + 8) * PITCH + jd * 8 + 2 * t) =
                    make_float2(oacc[mb][jd][2], oacc[mb][jd][3]);
            }
        }
    }
    __syncthreads();
    if (wn == 0) {
        #pragma unroll
        for (int mb = 0; mb < 2; mb++) {
            int r = wm * 32 + mb * 16 + g;
            float i0v = linv[r], i1v = linv[r + 8];
            float* og0 = g_o + (size_t)(b * NQ + q0 + r) * DM + h * DH;
            float* og1 = og0 + 8 * DM;
            #pragma unroll
            for (int jd = 0; jd < 8; jd++) {
                float2 e0 = *(float2*)(smf + r * PITCH + jd * 8 + 2 * t);
                float2 e1 = *(float2*)(smf + (r + 8) * PITCH + jd * 8 + 2 * t);
                *(float2*)(og0 + jd * 8 + 2 * t) = make_float2(
                    (oacc[mb][jd][0] + e0.x) * i0v, (oacc[mb][jd][1] + e0.y) * i0v);
                *(float2*)(og1 + jd * 8 + 2 * t) = make_float2(
                    (oacc[mb][jd][2] + e1.x) * i1v, (oacc[mb][jd][3] + e1.y) * i1v);
            }
        }
    }
}

// ===========================================================================
// Streaming normalize: attn[h,b,i,:] /= l[b,h,i]
// ===========================================================================
__global__ __launch_bounds__(256) void norm_attn(float* __restrict__ attn)
{
    size_t idx = (size_t)blockIdx.x * blockDim.x + threadIdx.x;
    size_t rowi = idx >> 10;
    int i  = (int)(rowi & (NQ - 1));
    int hb = (int)(rowi >> 12);
    int h = hb >> 1, b = hb & 1;
    float inv = 1.0f / g_l[(size_t)(b * NH + h) * NQ + i];
    float4 v = __ldcs((const float4*)attn + idx);
    v.x *= inv; v.y *= inv; v.z *= inv; v.w *= inv;
    __stcs((float4*)attn + idx, v);
}

extern "C" void kernel_launch(void* const* d_in, const int* in_sizes, int n_in,
                              void* d_out, int out_size)
{
    const float* q  = (const float*)d_in[0];
    const float* k  = (const float*)d_in[1];
    const float* v  = (const float*)d_in[2];
    const unsigned char* mask = (const unsigned char*)d_in[3];
    const float* Wq = (const float*)d_in[4];
    const float* bq = (const float*)d_in[5];
    const float* Wk = (const float*)d_in[6];
    const float* bk = (const float*)d_in[7];
    const float* Wv = (const float*)d_in[8];
    const float* bv = (const float*)d_in[9];
    const float* Wo = (const float*)d_in[10];
    const float* bo = (const float*)d_in[11];

    float* outbuf = (float*)d_out;
    float* attn = outbuf;
    float* outp = outbuf + ATTN_ELEMS;

    float *gq, *gk, *gv, *go;
    cudaGetSymbolAddress((void**)&gq, g_q);
    cudaGetSymbolAddress((void**)&gk, g_k);
    cudaGetSymbolAddress((void**)&gv, g_v);
    cudaGetSymbolAddress((void**)&go, g_o);

    cudaFuncSetAttribute(gemm_tc,
        cudaFuncAttributeMaxDynamicSharedMemorySize, GSM_BYTES);
    cudaFuncSetAttribute(attn_mma,
        cudaFuncAttributeMaxDynamicSharedMemorySize, SM_BYTES);

    dim3 gproj(DM / 64, MROWS / 64);

    gemm_tc<<<gproj, 128, GSM_BYTES>>>(q, Wq, bq, gq, 1);
    gemm_tc<<<gproj, 128, GSM_BYTES>>>(k, Wk, bk, gk, 1);
    gemm_tc<<<gproj, 128, GSM_BYTES>>>(v, Wv, bv, gv, 2);   // transposed per head

    attn_mma<<<dim3(BB * NH, NQ / QROWS), 128, SM_BYTES>>>(mask, attn);

    norm_attn<<<(unsigned)(ATTN_ELEMS / 4 / 256), 256>>>(attn);

    gemm_tc<<<gproj, 128, GSM_BYTES>>>(go, Wo, bo, outp, 0);
}

// round 9
// speedup vs baseline: 1.0758x; 1.0758x over previous
#include <cuda_runtime.h>
#include <math.h>
#include <stdint.h>

#define BB 2
#define NH 8
#define DH 64
#define DM 512
#define NQ 4096
#define NKK 4096
#define MROWS (BB*NQ)                       // 8192
#define ATTN_ELEMS ((size_t)NH*BB*(size_t)NQ*(size_t)NKK)   // 268435456

// scratch (device globals; no allocation allowed)
__device__ float g_q[BB*NH*NQ*DH];   // d-permuted within 8-blocks
__device__ float g_k[BB*NH*NKK*DH];  // d-permuted within 8-blocks
__device__ float g_v[BB*NH*NKK*DH];  // TRANSPOSED per head: [bh][d][n]
__device__ float g_o[MROWS*DM];

// ===========================================================================
// helpers
// ===========================================================================
__device__ __forceinline__ uint32_t s2u(const void* p){
    uint32_t a;
    asm("{ .reg .u64 t; cvta.to.shared.u64 t, %1; cvt.u32.u64 %0, t; }"
        : "=r"(a) : "l"(p));
    return a;
}
__device__ __forceinline__ uint32_t f2tf(float f){
    uint32_t u; asm("cvt.rna.tf32.f32 %0, %1;" : "=r"(u) : "f"(f)); return u;
}
__device__ __forceinline__ float ex2f(float x){
    float y; asm("ex2.approx.ftz.f32 %0, %1;" : "=f"(y) : "f"(x)); return y;
}
__device__ __forceinline__ void mma8(float* d, const uint32_t* a,
                                     uint32_t b0, uint32_t b1){
    asm volatile("mma.sync.aligned.m16n8k8.row.col.f32.tf32.tf32.f32 "
        "{%0,%1,%2,%3}, {%4,%5,%6,%7}, {%8,%9}, {%0,%1,%2,%3};"
        : "+f"(d[0]), "+f"(d[1]), "+f"(d[2]), "+f"(d[3])
        : "r"(a[0]), "r"(a[1]), "r"(a[2]), "r"(a[3]), "r"(b0), "r"(b1));
}
__device__ __forceinline__ void cpa16(uint32_t s, const void* g){
    asm volatile("cp.async.cg.shared.global [%0], [%1], 16;" :: "r"(s), "l"(g));
}
#define CP_COMMIT() asm volatile("cp.async.commit_group;" ::: "memory")
#define CP_WAIT(n)  asm volatile("cp.async.wait_group %0;" :: "n"(n) : "memory")

// ===========================================================================
// NT GEMM with bias: C[M,512] = A[M,512] @ W[512,512]^T + bias  (SIMT fp32)
// split=1: head-split [bh][n][d] with d permuted within 8-blocks
// split=2: head-split transposed [bh][d][n]
// split=0: plain row-major
// ===========================================================================
__global__ __launch_bounds__(256) void gemm_nt(
    const float* __restrict__ A, const float* __restrict__ W,
    const float* __restrict__ bias, float* __restrict__ C, int split)
{
    __shared__ float As[64][17];
    __shared__ float Ws[64][17];

    int i0 = blockIdx.y * 64;
    int j0 = blockIdx.x * 64;
    int tx = threadIdx.x, ty = threadIdx.y;
    int t  = ty * 16 + tx;
    int lr = t >> 2;
    int lk = (t & 3) * 4;

    float acc[4][4] = {};

    for (int k0 = 0; k0 < DM; k0 += 16) {
        float4 av = *(const float4*)(A + (size_t)(i0 + lr) * DM + k0 + lk);
        float4 wv = *(const float4*)(W + (size_t)(j0 + lr) * DM + k0 + lk);
        As[lr][lk+0]=av.x; As[lr][lk+1]=av.y; As[lr][lk+2]=av.z; As[lr][lk+3]=av.w;
        Ws[lr][lk+0]=wv.x; Ws[lr][lk+1]=wv.y; Ws[lr][lk+2]=wv.z; Ws[lr][lk+3]=wv.w;
        __syncthreads();
        #pragma unroll
        for (int kk = 0; kk < 16; kk++) {
            float a[4], w[4];
            #pragma unroll
            for (int aa = 0; aa < 4; aa++) a[aa] = As[ty*4+aa][kk];
            #pragma unroll
            for (int cc = 0; cc < 4; cc++) w[cc] = Ws[tx*4+cc][kk];
            #pragma unroll
            for (int aa = 0; aa < 4; aa++)
                #pragma unroll
                for (int cc = 0; cc < 4; cc++)
                    acc[aa][cc] += a[aa] * w[cc];
        }
        __syncthreads();
    }

    int j = j0 + tx * 4;
    float4 bv = *(const float4*)(bias + j);
    #pragma unroll
    for (int aa = 0; aa < 4; aa++) {
        int i = i0 + ty * 4 + aa;
        float4 r = make_float4(acc[aa][0]+bv.x, acc[aa][1]+bv.y,
                               acc[aa][2]+bv.z, acc[aa][3]+bv.w);
        if (split == 1) {
            int b = i >> 12, il = i & (NQ-1);
            int h = j >> 6,  d  = j & (DH-1);
            int dpos = (d & ~7) | ((d >> 2) & 1);
            float* cb = C + (((size_t)(b*NH + h)*NQ + il)*DH + dpos);
            cb[0] = r.x; cb[2] = r.y; cb[4] = r.z; cb[6] = r.w;
        } else if (split == 2) {
            int b = i >> 12, il = i & (NQ-1);
            int h = j >> 6,  d  = j & (DH-1);
            float* p = C + ((size_t)(b*NH + h)*DH + d) * (size_t)NQ + il;
            p[0] = r.x; p[(size_t)NQ] = r.y;
            p[2*(size_t)NQ] = r.z; p[3*(size_t)NQ] = r.w;
        } else {
            *(float4*)(C + (size_t)i * DM + j) = r;
        }
    }
}

// ===========================================================================
// mma.sync tf32 attention. 128 threads / 4 warps (2m x 2n), 64 q-rows per
// CTA, 2 CTAs per SM. Warp tile 32q x 32n. Shuffle-free PV via
// k-permutation; LDS.64-paired fragments; P = ex2(S) with Q pre-scaled by
// 0.125*log2(e); unnormalized P streamed to gmem.
// NEW: each CTA normalizes its own 64-row P slab in a fused tail loop
// (overlaps the SM-partner CTA's compute) — the separate norm pass is gone.
// ===========================================================================
#define PITCH 72                 // floats per smem row (288B)
#define TILEB (64*PITCH*4)       // 18432 B per tile buffer
#define KOFF(buf)  ((buf)*TILEB)
#define VOFF(buf)  (2*TILEB + (buf)*TILEB)
#define LSUM_F     (4*TILEB/4)           // float index
#define LINV_F     (LSUM_F + 128)
#define SM_BYTES   (4*TILEB + (128+64)*4)
#define NT         (NKK/64)              // 64 k-tiles
#define QSCALE     0.18033688f           // 0.125 * log2(e)
#define QROWS      64

__global__ __launch_bounds__(128, 2) void attn_mma(
    const unsigned char* __restrict__ mask, float* __restrict__ attn)
{
    extern __shared__ float smf[];
    uint32_t sb = s2u(smf);

    int tid  = threadIdx.x;
    int w    = tid >> 5, lane = tid & 31;
    int wm   = w >> 1,  wn = w & 1;
    int g    = lane >> 2, t = lane & 3;

    int bh = blockIdx.x;               // bh fastest -> K/V L2 sharing
    int b  = bh >> 3, h = bh & 7;
    int q0 = blockIdx.y * QROWS;

    const float* qg  = g_q + ((size_t)bh * NQ + q0) * DH;
    const float* kg  = g_k + (size_t)bh * NKK * DH;     // [n][d] (d permuted)
    const float* vtg = g_v + (size_t)bh * DH * NKK;     // [d][n]
    float* ab = attn + (size_t)(h * BB + b) * NQ * NKK;
    const unsigned char* mbase = mask + (size_t)b * NQ * NKK;

    // ---- stage Q (64 x 64) into smem, pre-scaled ----
    #pragma unroll
    for (int i = 0; i < 8; i++) {
        int idx = tid + i * 128;           // 1024 float4
        int r = idx >> 4, c4 = (idx & 15) << 2;
        float4 v = *(const float4*)(qg + (size_t)r * DH + c4);
        v.x *= QSCALE; v.y *= QSCALE; v.z *= QSCALE; v.w *= QSCALE;
        *(float4*)(smf + r * PITCH + c4) = v;
    }
    __syncthreads();

    // ---- preload Q A-fragments (tf32) via paired LDS.64 ----
    uint32_t qa[2][8][4];
    #pragma unroll
    for (int mb = 0; mb < 2; mb++) {
        int R = wm * 32 + mb * 16 + g;
        #pragma unroll
        for (int s = 0; s < 8; s++) {
            float2 lo = *(const float2*)(smf + R * PITCH + s * 8 + 2 * t);
            float2 hi = *(const float2*)(smf + (R + 8) * PITCH + s * 8 + 2 * t);
            qa[mb][s][0] = f2tf(lo.x);
            qa[mb][s][1] = f2tf(hi.x);
            qa[mb][s][2] = f2tf(lo.y);
            qa[mb][s][3] = f2tf(hi.y);
        }
    }
    __syncthreads();

    float oacc[2][8][4] = {};
    float lacc[2][2] = {};

    // ---- prologue: tile 0 (K rows + VT rows) ----
    #pragma unroll
    for (int i = 0; i < 8; i++) {
        int c = tid + i * 128;              // 1024 chunks of 16B per tensor
        int r = c >> 4, c16 = c & 15;
        cpa16(sb + KOFF(0) + (uint32_t)(r * PITCH + c16 * 4) * 4,
              kg + (size_t)r * DH + c16 * 4);
        cpa16(sb + VOFF(0) + (uint32_t)(r * PITCH + c16 * 4) * 4,
              vtg + (size_t)r * NKK + c16 * 4);
    }
    CP_COMMIT();

    for (int it = 0; it < NT; it++) {
        int buf = it & 1;
        CP_WAIT(0);
        __syncthreads();                    // data ready + prev buffer consumed
        if (it + 1 < NT) {
            int j0n = (it + 1) * 64, nb = buf ^ 1;
            #pragma unroll
            for (int i = 0; i < 8; i++) {
                int c = tid + i * 128;
                int r = c >> 4, c16 = c & 15;
                cpa16(sb + KOFF(nb) + (uint32_t)(r * PITCH + c16 * 4) * 4,
                      kg + (size_t)(j0n + r) * DH + c16 * 4);
                cpa16(sb + VOFF(nb) + (uint32_t)(r * PITCH + c16 * 4) * 4,
                      vtg + (size_t)r * NKK + j0n + c16 * 4);
            }
            CP_COMMIT();
        }

        const float* Ks = smf + KOFF(buf) / 4;
        const float* Vs = smf + VOFF(buf) / 4;   // [d-row][k-col]

        // ---- QK^T (paired B-frags: one LDS.64 each) ----
        float sacc[2][4][4] = {};
        #pragma unroll
        for (int s = 0; s < 8; s++) {
            #pragma unroll
            for (int j = 0; j < 4; j++) {
                int n0 = wn * 32 + j * 8;
                float2 kv = *(const float2*)(Ks + (n0 + g) * PITCH + s * 8 + 2 * t);
                uint32_t b0 = __float_as_uint(kv.x);
                uint32_t b1 = __float_as_uint(kv.y);
                mma8(sacc[0][j], qa[0][s], b0, b1);
                mma8(sacc[1][j], qa[1][s], b0, b1);
            }
        }

        // ---- epilogue + PV (shuffle-free, paired V B-frags) ----
        int jg0 = it * 64 + wn * 32;
        #pragma unroll
        for (int j = 0; j < 4; j++) {
            uint32_t pa[2][4];
            #pragma unroll
            for (int mb = 0; mb < 2; mb++) {
                int r0 = q0 + wm * 32 + mb * 16 + g;
                int colg = jg0 + j * 8 + 2 * t;
                const unsigned char* m0 = mbase + (size_t)r0 * NKK + colg;
                unsigned short mv0 = *(const unsigned short*)m0;
                unsigned short mv1 = *(const unsigned short*)(m0 + 8 * NKK);
                float* s4 = sacc[mb][j];
                float p0 = (mv0 & 0xff) ? 0.f : ex2f(s4[0]);
                float p1 = (mv0 >> 8)   ? 0.f : ex2f(s4[1]);
                float p2 = (mv1 & 0xff) ? 0.f : ex2f(s4[2]);
                float p3 = (mv1 >> 8)   ? 0.f : ex2f(s4[3]);
                lacc[mb][0] += p0 + p1;
                lacc[mb][1] += p2 + p3;
                __stcs((float2*)(ab + (size_t)r0 * NKK + colg), make_float2(p0, p1));
                __stcs((float2*)(ab + (size_t)(r0 + 8) * NKK + colg), make_float2(p2, p3));
                pa[mb][0] = f2tf(p0);
                pa[mb][1] = f2tf(p2);
                pa[mb][2] = f2tf(p1);
                pa[mb][3] = f2tf(p3);
            }
            int k0 = wn * 32 + j * 8;
            #pragma unroll
            for (int jd = 0; jd < 8; jd++) {
                float2 vv = *(const float2*)(Vs + (jd * 8 + g) * PITCH + k0 + 2 * t);
                uint32_t b0 = __float_as_uint(vv.x);
                uint32_t b1 = __float_as_uint(vv.y);
                mma8(oacc[0][jd], pa[0], b0, b1);
                mma8(oacc[1][jd], pa[1], b0, b1);
            }
        }
    }

    // ---- rowsum reduce ----
    #pragma unroll
    for (int off = 1; off <= 2; off <<= 1) {
        #pragma unroll
        for (int mb = 0; mb < 2; mb++) {
            lacc[mb][0] += __shfl_xor_sync(0xffffffffu, lacc[mb][0], off);
            lacc[mb][1] += __shfl_xor_sync(0xffffffffu, lacc[mb][1], off);
        }
    }
    float* lsum = smf + LSUM_F;
    float* linv = smf + LINV_F;
    __syncthreads();
    if (t == 0) {
        #pragma unroll
        for (int mb = 0; mb < 2; mb++) {
            lsum[wn * 64 + wm * 32 + mb * 16 + g]     = lacc[mb][0];
            lsum[wn * 64 + wm * 32 + mb * 16 + g + 8] = lacc[mb][1];
        }
    }
    __syncthreads();
    if (tid < QROWS) {
        linv[tid] = 1.0f / (lsum[tid] + lsum[64 + tid]);
    }
    __syncthreads();

    // ---- cross-warp(n) O reduction via smem (reuse KV region) ----
    if (wn == 1) {
        #pragma unroll
        for (int mb = 0; mb < 2; mb++) {
            int r = wm * 32 + mb * 16 + g;
            #pragma unroll
            for (int jd = 0; jd < 8; jd++) {
                *(float2*)(smf + r * PITCH + jd * 8 + 2 * t) =
                    make_float2(oacc[mb][jd][0], oacc[mb][jd][1]);
                *(float2*)(smf + (r + 8) * PITCH + jd * 8 + 2 * t) =
                    make_float2(oacc[mb][jd][2], oacc[mb][jd][3]);
            }
        }
    }
    __syncthreads();
    if (wn == 0) {
        #pragma unroll
        for (int mb = 0; mb < 2; mb++) {
            int r = wm * 32 + mb * 16 + g;
            float i0v = linv[r], i1v = linv[r + 8];
            float* og0 = g_o + (size_t)(b * NQ + q0 + r) * DM + h * DH;
            float* og1 = og0 + 8 * DM;
            #pragma unroll
            for (int jd = 0; jd < 8; jd++) {
                float2 e0 = *(float2*)(smf + r * PITCH + jd * 8 + 2 * t);
                float2 e1 = *(float2*)(smf + (r + 8) * PITCH + jd * 8 + 2 * t);
                *(float2*)(og0 + jd * 8 + 2 * t) = make_float2(
                    (oacc[mb][jd][0] + e0.x) * i0v, (oacc[mb][jd][1] + e0.y) * i0v);
                *(float2*)(og1 + jd * 8 + 2 * t) = make_float2(
                    (oacc[mb][jd][2] + e1.x) * i1v, (oacc[mb][jd][3] + e1.y) * i1v);
            }
        }
    }

    // ---- fused normalize of this CTA's own 64-row P slab ----
    // __syncthreads above made the block's prior global P stores visible.
    {
        float4* abq = (float4*)(ab + (size_t)q0 * NKK);   // 64 rows x 1024 float4
        for (int i = tid; i < QROWS * 1024; i += 128) {
            int r = i >> 10;
            float inv = linv[r];
            float4 v = __ldcs(abq + i);
            v.x *= inv; v.y *= inv; v.z *= inv; v.w *= inv;
            __stcs(abq + i, v);
        }
    }
}

extern "C" void kernel_launch(void* const* d_in, const int* in_sizes, int n_in,
                              void* d_out, int out_size)
{
    const float* q  = (const float*)d_in[0];
    const float* k  = (const float*)d_in[1];
    const float* v  = (const float*)d_in[2];
    const unsigned char* mask = (const unsigned char*)d_in[3];
    const float* Wq = (const float*)d_in[4];
    const float* bq = (const float*)d_in[5];
    const float* Wk = (const float*)d_in[6];
    const float* bk = (const float*)d_in[7];
    const float* Wv = (const float*)d_in[8];
    const float* bv = (const float*)d_in[9];
    const float* Wo = (const float*)d_in[10];
    const float* bo = (const float*)d_in[11];

    float* outbuf = (float*)d_out;
    float* attn = outbuf;
    float* outp = outbuf + ATTN_ELEMS;

    float *gq, *gk, *gv, *go;
    cudaGetSymbolAddress((void**)&gq, g_q);
    cudaGetSymbolAddress((void**)&gk, g_k);
    cudaGetSymbolAddress((void**)&gv, g_v);
    cudaGetSymbolAddress((void**)&go, g_o);

    dim3 blk(16, 16);
    dim3 gproj(DM / 64, MROWS / 64);

    gemm_nt<<<gproj, blk>>>(q, Wq, bq, gq, 1);
    gemm_nt<<<gproj, blk>>>(k, Wk, bk, gk, 1);
    gemm_nt<<<gproj, blk>>>(v, Wv, bv, gv, 2);   // transposed per head

    cudaFuncSetAttribute(attn_mma,
        cudaFuncAttributeMaxDynamicSharedMemorySize, SM_BYTES);
    attn_mma<<<dim3(BB * NH, NQ / QROWS), 128, SM_BYTES>>>(mask, attn);

    gemm_nt<<<gproj, blk>>>(go, Wo, bo, outp, 0);
}

// round 11
// speedup vs baseline: 1.1292x; 1.0497x over previous
#include <cuda_runtime.h>
#include <math.h>
#include <stdint.h>

#define BB 2
#define NH 8
#define DH 64
#define DM 512
#define NQ 4096
#define NKK 4096
#define MROWS (BB*NQ)                       // 8192
#define ATTN_ELEMS ((size_t)NH*BB*(size_t)NQ*(size_t)NKK)   // 268435456

// scratch (device globals; no allocation allowed)
__device__ float g_q[BB*NH*NQ*DH];   // d-permuted within 8-blocks
__device__ float g_k[BB*NH*NKK*DH];  // d-permuted within 8-blocks
__device__ float g_v[BB*NH*NKK*DH];  // TRANSPOSED per head: [bh][d][n]
__device__ float g_o[MROWS*DM];
__device__ float g_l[BB*NH*NQ];

// ===========================================================================
// helpers
// ===========================================================================
__device__ __forceinline__ uint32_t s2u(const void* p){
    uint32_t a;
    asm("{ .reg .u64 t; cvta.to.shared.u64 t, %1; cvt.u32.u64 %0, t; }"
        : "=r"(a) : "l"(p));
    return a;
}
__device__ __forceinline__ uint32_t f2tf(float f){
    uint32_t u; asm("cvt.rna.tf32.f32 %0, %1;" : "=r"(u) : "f"(f)); return u;
}
__device__ __forceinline__ float ex2f(float x){
    float y; asm("ex2.approx.ftz.f32 %0, %1;" : "=f"(y) : "f"(x)); return y;
}
__device__ __forceinline__ void mma8(float* d, const uint32_t* a,
                                     uint32_t b0, uint32_t b1){
    asm volatile("mma.sync.aligned.m16n8k8.row.col.f32.tf32.tf32.f32 "
        "{%0,%1,%2,%3}, {%4,%5,%6,%7}, {%8,%9}, {%0,%1,%2,%3};"
        : "+f"(d[0]), "+f"(d[1]), "+f"(d[2]), "+f"(d[3])
        : "r"(a[0]), "r"(a[1]), "r"(a[2]), "r"(a[3]), "r"(b0), "r"(b1));
}
__device__ __forceinline__ void cpa16(uint32_t s, const void* g){
    asm volatile("cp.async.cg.shared.global [%0], [%1], 16;" :: "r"(s), "l"(g));
}
#define CP_COMMIT() asm volatile("cp.async.commit_group;" ::: "memory")
#define CP_WAIT(n)  asm volatile("cp.async.wait_group %0;" :: "n"(n) : "memory")

// ===========================================================================
// NT GEMM with bias: C[M,512] = A[M,512] @ W[512,512]^T + bias  (SIMT fp32)
// split=1: head-split [bh][n][d] with d permuted within 8-blocks
// split=2: head-split transposed [bh][d][n]
// split=0: plain row-major
// ===========================================================================
__global__ __launch_bounds__(256) void gemm_nt(
    const float* __restrict__ A, const float* __restrict__ W,
    const float* __restrict__ bias, float* __restrict__ C, int split)
{
    __shared__ float As[64][17];
    __shared__ float Ws[64][17];

    int i0 = blockIdx.y * 64;
    int j0 = blockIdx.x * 64;
    int tx = threadIdx.x, ty = threadIdx.y;
    int t  = ty * 16 + tx;
    int lr = t >> 2;
    int lk = (t & 3) * 4;

    float acc[4][4] = {};

    for (int k0 = 0; k0 < DM; k0 += 16) {
        float4 av = *(const float4*)(A + (size_t)(i0 + lr) * DM + k0 + lk);
        float4 wv = *(const float4*)(W + (size_t)(j0 + lr) * DM + k0 + lk);
        As[lr][lk+0]=av.x; As[lr][lk+1]=av.y; As[lr][lk+2]=av.z; As[lr][lk+3]=av.w;
        Ws[lr][lk+0]=wv.x; Ws[lr][lk+1]=wv.y; Ws[lr][lk+2]=wv.z; Ws[lr][lk+3]=wv.w;
        __syncthreads();
        #pragma unroll
        for (int kk = 0; kk < 16; kk++) {
            float a[4], w[4];
            #pragma unroll
            for (int aa = 0; aa < 4; aa++) a[aa] = As[ty*4+aa][kk];
            #pragma unroll
            for (int cc = 0; cc < 4; cc++) w[cc] = Ws[tx*4+cc][kk];
            #pragma unroll
            for (int aa = 0; aa < 4; aa++)
                #pragma unroll
                for (int cc = 0; cc < 4; cc++)
                    acc[aa][cc] += a[aa] * w[cc];
        }
        __syncthreads();
    }

    int j = j0 + tx * 4;
    float4 bv = *(const float4*)(bias + j);
    #pragma unroll
    for (int aa = 0; aa < 4; aa++) {
        int i = i0 + ty * 4 + aa;
        float4 r = make_float4(acc[aa][0]+bv.x, acc[aa][1]+bv.y,
                               acc[aa][2]+bv.z, acc[aa][3]+bv.w);
        if (split == 1) {
            int b = i >> 12, il = i & (NQ-1);
            int h = j >> 6,  d  = j & (DH-1);
            int dpos = (d & ~7) | ((d >> 2) & 1);
            float* cb = C + (((size_t)(b*NH + h)*NQ + il)*DH + dpos);
            cb[0] = r.x; cb[2] = r.y; cb[4] = r.z; cb[6] = r.w;
        } else if (split == 2) {
            int b = i >> 12, il = i & (NQ-1);
            int h = j >> 6,  d  = j & (DH-1);
            float* p = C + ((size_t)(b*NH + h)*DH + d) * (size_t)NQ + il;
            p[0] = r.x; p[(size_t)NQ] = r.y;
            p[2*(size_t)NQ] = r.z; p[3*(size_t)NQ] = r.w;
        } else {
            *(float4*)(C + (size_t)i * DM + j) = r;
        }
    }
}

// ===========================================================================
// mma.sync tf32 attention. 128 threads / 4 warps (2m x 2n), 64 q-rows per
// CTA, 2 CTAs per SM. Warp tile 32q x 32n. Shuffle-free PV via
// k-permutation; LDS.64-paired fragments; P = ex2(S) with Q pre-scaled by
// 0.125*log2(e); unnormalized P streamed to gmem; separate norm pass.
// R10: mask tile pitch 80B (16B-aligned cp.async dests, conflict-free
// LDS.16); P A-frags bit-cast (no cvt); mask via cp.async pipeline.
// ===========================================================================
#define PITCH 72                 // floats per smem row (288B)
#define TILEB (64*PITCH*4)       // 18432 B per tile buffer
#define MPITCH 80                // mask tile pitch in bytes (16B multiple)
#define MTILEB (64*MPITCH)       // 5120 B mask tile
#define KOFF(buf)  ((buf)*TILEB)
#define VOFF(buf)  (2*TILEB + (buf)*TILEB)
#define MOFF(buf)  (4*TILEB + (buf)*MTILEB)
#define LSUM_F     ((4*TILEB + 2*MTILEB)/4)      // float index
#define LINV_F     (LSUM_F + 128)
#define SM_BYTES   (4*TILEB + 2*MTILEB + (128+64)*4)
#define NT         (NKK/64)              // 64 k-tiles
#define QSCALE     0.18033688f           // 0.125 * log2(e)
#define QROWS      64

__global__ __launch_bounds__(128, 2) void attn_mma(
    const unsigned char* __restrict__ mask, float* __restrict__ attn)
{
    extern __shared__ float smf[];
    uint32_t sb = s2u(smf);
    const unsigned char* smb = (const unsigned char*)smf;

    int tid  = threadIdx.x;
    int w    = tid >> 5, lane = tid & 31;
    int wm   = w >> 1,  wn = w & 1;
    int g    = lane >> 2, t = lane & 3;

    int bh = blockIdx.x;               // bh fastest -> K/V L2 sharing
    int b  = bh >> 3, h = bh & 7;
    int q0 = blockIdx.y * QROWS;

    const float* qg  = g_q + ((size_t)bh * NQ + q0) * DH;
    const float* kg  = g_k + (size_t)bh * NKK * DH;     // [n][d] (d permuted)
    const float* vtg = g_v + (size_t)bh * DH * NKK;     // [d][n]
    float* ab = attn + (size_t)(h * BB + b) * NQ * NKK;
    const unsigned char* mbase = mask + ((size_t)b * NQ + q0) * NKK;

    // ---- stage Q (64 x 64) into smem, pre-scaled ----
    #pragma unroll
    for (int i = 0; i < 8; i++) {
        int idx = tid + i * 128;           // 1024 float4
        int r = idx >> 4, c4 = (idx & 15) << 2;
        float4 v = *(const float4*)(qg + (size_t)r * DH + c4);
        v.x *= QSCALE; v.y *= QSCALE; v.z *= QSCALE; v.w *= QSCALE;
        *(float4*)(smf + r * PITCH + c4) = v;
    }
    __syncthreads();

    // ---- preload Q A-fragments (tf32) via paired LDS.64 ----
    uint32_t qa[2][8][4];
    #pragma unroll
    for (int mb = 0; mb < 2; mb++) {
        int R = wm * 32 + mb * 16 + g;
        #pragma unroll
        for (int s = 0; s < 8; s++) {
            float2 lo = *(const float2*)(smf + R * PITCH + s * 8 + 2 * t);
            float2 hi = *(const float2*)(smf + (R + 8) * PITCH + s * 8 + 2 * t);
            qa[mb][s][0] = f2tf(lo.x);
            qa[mb][s][1] = f2tf(hi.x);
            qa[mb][s][2] = f2tf(lo.y);
            qa[mb][s][3] = f2tf(hi.y);
        }
    }
    __syncthreads();

    float oacc[2][8][4] = {};
    float lacc[2][2] = {};

    // ---- prologue: tile 0 (K rows + VT rows + mask tile) ----
    #pragma unroll
    for (int i = 0; i < 8; i++) {
        int c = tid + i * 128;              // 1024 chunks of 16B per tensor
        int r = c >> 4, c16 = c & 15;
        cpa16(sb + KOFF(0) + (uint32_t)(r * PITCH + c16 * 4) * 4,
              kg + (size_t)r * DH + c16 * 4);
        cpa16(sb + VOFF(0) + (uint32_t)(r * PITCH + c16 * 4) * 4,
              vtg + (size_t)r * NKK + c16 * 4);
    }
    #pragma unroll
    for (int i = 0; i < 2; i++) {           // 256 chunks of 16B (mask 64x64B)
        int c = tid + i * 128;
        int r = c >> 2, cb16 = (c & 3) * 16;
        cpa16(sb + MOFF(0) + (uint32_t)(r * MPITCH + cb16),
              mbase + (size_t)r * NKK + cb16);
    }
    CP_COMMIT();

    for (int it = 0; it < NT; it++) {
        int buf = it & 1;
        CP_WAIT(0);
        __syncthreads();                    // data ready + prev buffer consumed
        if (it + 1 < NT) {
            int j0n = (it + 1) * 64, nb = buf ^ 1;
            #pragma unroll
            for (int i = 0; i < 8; i++) {
                int c = tid + i * 128;
                int r = c >> 4, c16 = c & 15;
                cpa16(sb + KOFF(nb) + (uint32_t)(r * PITCH + c16 * 4) * 4,
                      kg + (size_t)(j0n + r) * DH + c16 * 4);
                cpa16(sb + VOFF(nb) + (uint32_t)(r * PITCH + c16 * 4) * 4,
                      vtg + (size_t)r * NKK + j0n + c16 * 4);
            }
            #pragma unroll
            for (int i = 0; i < 2; i++) {
                int c = tid + i * 128;
                int r = c >> 2, cb16 = (c & 3) * 16;
                cpa16(sb + MOFF(nb) + (uint32_t)(r * MPITCH + cb16),
                      mbase + (size_t)r * NKK + j0n + cb16);
            }
            CP_COMMIT();
        }

        const float* Ks = smf + KOFF(buf) / 4;
        const float* Vs = smf + VOFF(buf) / 4;   // [d-row][k-col]
        const unsigned char* Ms = smb + MOFF(buf);

        // ---- QK^T (paired B-frags: one LDS.64 each) ----
        float sacc[2][4][4] = {};
        #pragma unroll
        for (int s = 0; s < 8; s++) {
            #pragma unroll
            for (int j = 0; j < 4; j++) {
                int n0 = wn * 32 + j * 8;
                float2 kv = *(const float2*)(Ks + (n0 + g) * PITCH + s * 8 + 2 * t);
                uint32_t b0 = __float_as_uint(kv.x);
                uint32_t b1 = __float_as_uint(kv.y);
                mma8(sacc[0][j], qa[0][s], b0, b1);
                mma8(sacc[1][j], qa[1][s], b0, b1);
            }
        }

        // ---- epilogue + PV (shuffle-free, bit-cast A-frags, smem mask) ----
        int jg0 = it * 64 + wn * 32;
        #pragma unroll
        for (int j = 0; j < 4; j++) {
            uint32_t pa[2][4];
            #pragma unroll
            for (int mb = 0; mb < 2; mb++) {
                int rl = wm * 32 + mb * 16 + g;        // row within CTA tile
                int r0 = q0 + rl;
                int colg = jg0 + j * 8 + 2 * t;
                int coll = wn * 32 + j * 8 + 2 * t;    // col within tile
                unsigned short mv0 = *(const unsigned short*)(Ms + rl * MPITCH + coll);
                unsigned short mv1 = *(const unsigned short*)(Ms + (rl + 8) * MPITCH + coll);
                float* s4 = sacc[mb][j];
                float p0 = (mv0 & 0xff) ? 0.f : ex2f(s4[0]);
                float p1 = (mv0 >> 8)   ? 0.f : ex2f(s4[1]);
                float p2 = (mv1 & 0xff) ? 0.f : ex2f(s4[2]);
                float p3 = (mv1 >> 8)   ? 0.f : ex2f(s4[3]);
                lacc[mb][0] += p0 + p1;
                lacc[mb][1] += p2 + p3;
                __stcs((float2*)(ab + (size_t)r0 * NKK + colg), make_float2(p0, p1));
                __stcs((float2*)(ab + (size_t)(r0 + 8) * NKK + colg), make_float2(p2, p3));
                pa[mb][0] = __float_as_uint(p0);
                pa[mb][1] = __float_as_uint(p2);
                pa[mb][2] = __float_as_uint(p1);
                pa[mb][3] = __float_as_uint(p3);
            }
            int k0 = wn * 32 + j * 8;
            #pragma unroll
            for (int jd = 0; jd < 8; jd++) {
                float2 vv = *(const float2*)(Vs + (jd * 8 + g) * PITCH + k0 + 2 * t);
                uint32_t b0 = __float_as_uint(vv.x);
                uint32_t b1 = __float_as_uint(vv.y);
                mma8(oacc[0][jd], pa[0], b0, b1);
                mma8(oacc[1][jd], pa[1], b0, b1);
            }
        }
    }

    // ---- rowsum reduce ----
    #pragma unroll
    for (int off = 1; off <= 2; off <<= 1) {
        #pragma unroll
        for (int mb = 0; mb < 2; mb++) {
            lacc[mb][0] += __shfl_xor_sync(0xffffffffu, lacc[mb][0], off);
            lacc[mb][1] += __shfl_xor_sync(0xffffffffu, lacc[mb][1], off);
        }
    }
    float* lsum = smf + LSUM_F;
    float* linv = smf + LINV_F;
    __syncthreads();
    if (t == 0) {
        #pragma unroll
        for (int mb = 0; mb < 2; mb++) {
            lsum[wn * 64 + wm * 32 + mb * 16 + g]     = lacc[mb][0];
            lsum[wn * 64 + wm * 32 + mb * 16 + g + 8] = lacc[mb][1];
        }
    }
    __syncthreads();
    if (tid < QROWS) {
        float tot = lsum[tid] + lsum[64 + tid];
        g_l[(size_t)bh * NQ + q0 + tid] = tot;
        linv[tid] = 1.0f / tot;
    }
    __syncthreads();

    // ---- cross-warp(n) O reduction via smem (reuse KV region) ----
    if (wn == 1) {
        #pragma unroll
        for (int mb = 0; mb < 2; mb++) {
            int r = wm * 32 + mb * 16 + g;
            #pragma unroll
            for (int jd = 0; jd < 8; jd++) {
                *(float2*)(smf + r * PITCH + jd * 8 + 2 * t) =
                    make_float2(oacc[mb][jd][0], oacc[mb][jd][1]);
                *(float2*)(smf + (r + 8) * PITCH + jd * 8 + 2 * t) =
                    make_float2(oacc[mb][jd][2], oacc[mb][jd][3]);
            }
        }
    }
    __syncthreads();
    if (wn == 0) {
        #pragma unroll
        for (int mb = 0; mb < 2; mb++) {
            int r = wm * 32 + mb * 16 + g;
            float i0v = linv[r], i1v = linv[r + 8];
            float* og0 = g_o + (size_t)(b * NQ + q0 + r) * DM + h * DH;
            float* og1 = og0 + 8 * DM;
            #pragma unroll
            for (int jd = 0; jd < 8; jd++) {
                float2 e0 = *(float2*)(smf + r * PITCH + jd * 8 + 2 * t);
                float2 e1 = *(float2*)(smf + (r + 8) * PITCH + jd * 8 + 2 * t);
                *(float2*)(og0 + jd * 8 + 2 * t) = make_float2(
                    (oacc[mb][jd][0] + e0.x) * i0v, (oacc[mb][jd][1] + e0.y) * i0v);
                *(float2*)(og1 + jd * 8 + 2 * t) = make_float2(
                    (oacc[mb][jd][2] + e1.x) * i1v, (oacc[mb][jd][3] + e1.y) * i1v);
            }
        }
    }
}

// ===========================================================================
// Streaming normalize: attn[h,b,i,:] /= l[b,h,i]
// ===========================================================================
__global__ __launch_bounds__(256) void norm_attn(float* __restrict__ attn)
{
    size_t idx = (size_t)blockIdx.x * blockDim.x + threadIdx.x;
    size_t rowi = idx >> 10;
    int i  = (int)(rowi & (NQ - 1));
    int hb = (int)(rowi >> 12);
    int h = hb >> 1, b = hb & 1;
    float inv = 1.0f / g_l[(size_t)(b * NH + h) * NQ + i];
    float4 v = __ldcs((const float4*)attn + idx);
    v.x *= inv; v.y *= inv; v.z *= inv; v.w *= inv;
    __stcs((float4*)attn + idx, v);
}

extern "C" void kernel_launch(void* const* d_in, const int* in_sizes, int n_in,
                              void* d_out, int out_size)
{
    const float* q  = (const float*)d_in[0];
    const float* k  = (const float*)d_in[1];
    const float* v  = (const float*)d_in[2];
    const unsigned char* mask = (const unsigned char*)d_in[3];
    const float* Wq = (const float*)d_in[4];
    const float* bq = (const float*)d_in[5];
    const float* Wk = (const float*)d_in[6];
    const float* bk = (const float*)d_in[7];
    const float* Wv = (const float*)d_in[8];
    const float* bv = (const float*)d_in[9];
    const float* Wo = (const float*)d_in[10];
    const float* bo = (const float*)d_in[11];

    float* outbuf = (float*)d_out;
    float* attn = outbuf;
    float* outp = outbuf + ATTN_ELEMS;

    float *gq, *gk, *gv, *go;
    cudaGetSymbolAddress((void**)&gq, g_q);
    cudaGetSymbolAddress((void**)&gk, g_k);
    cudaGetSymbolAddress((void**)&gv, g_v);
    cudaGetSymbolAddress((void**)&go, g_o);

    dim3 blk(16, 16);
    dim3 gproj(DM / 64, MROWS / 64);

    gemm_nt<<<gproj, blk>>>(q, Wq, bq, gq, 1);
    gemm_nt<<<gproj, blk>>>(k, Wk, bk, gk, 1);
    gemm_nt<<<gproj, blk>>>(v, Wv, bv, gv, 2);   // transposed per head

    cudaFuncSetAttribute(attn_mma,
        cudaFuncAttributeMaxDynamicSharedMemorySize, SM_BYTES);
    attn_mma<<<dim3(BB * NH, NQ / QROWS), 128, SM_BYTES>>>(mask, attn);

    norm_attn<<<(unsigned)(ATTN_ELEMS / 4 / 256), 256>>>(attn);

    gemm_nt<<<gproj, blk>>>(go, Wo, bo, outp, 0);
}

// round 12
// speedup vs baseline: 1.1458x; 1.0147x over previous
#include <cuda_runtime.h>
#include <math.h>
#include <stdint.h>

#define BB 2
#define NH 8
#define DH 64
#define DM 512
#define NQ 4096
#define NKK 4096
#define MROWS (BB*NQ)                       // 8192
#define ATTN_ELEMS ((size_t)NH*BB*(size_t)NQ*(size_t)NKK)   // 268435456

// scratch (device globals; no allocation allowed)
__device__ float g_q[BB*NH*NQ*DH];   // d-permuted within 8-blocks
__device__ float g_k[BB*NH*NKK*DH];  // d-permuted within 8-blocks
__device__ float g_v[BB*NH*NKK*DH];  // TRANSPOSED per head: [bh][d][n]
__device__ float g_o[MROWS*DM];
__device__ float g_l[BB*NH*NQ];

// ===========================================================================
// helpers
// ===========================================================================
__device__ __forceinline__ uint32_t s2u(const void* p){
    uint32_t a;
    asm("{ .reg .u64 t; cvta.to.shared.u64 t, %1; cvt.u32.u64 %0, t; }"
        : "=r"(a) : "l"(p));
    return a;
}
__device__ __forceinline__ uint32_t f2tf(float f){
    uint32_t u; asm("cvt.rna.tf32.f32 %0, %1;" : "=r"(u) : "f"(f)); return u;
}
__device__ __forceinline__ float ex2f(float x){
    float y; asm("ex2.approx.ftz.f32 %0, %1;" : "=f"(y) : "f"(x)); return y;
}
__device__ __forceinline__ void mma8(float* d, const uint32_t* a,
                                     uint32_t b0, uint32_t b1){
    asm volatile("mma.sync.aligned.m16n8k8.row.col.f32.tf32.tf32.f32 "
        "{%0,%1,%2,%3}, {%4,%5,%6,%7}, {%8,%9}, {%0,%1,%2,%3};"
        : "+f"(d[0]), "+f"(d[1]), "+f"(d[2]), "+f"(d[3])
        : "r"(a[0]), "r"(a[1]), "r"(a[2]), "r"(a[3]), "r"(b0), "r"(b1));
}
__device__ __forceinline__ void cpa16(uint32_t s, const void* g){
    asm volatile("cp.async.cg.shared.global [%0], [%1], 16;" :: "r"(s), "l"(g));
}
#define CP_COMMIT() asm volatile("cp.async.commit_group;" ::: "memory")
#define CP_WAIT(n)  asm volatile("cp.async.wait_group %0;" :: "n"(n) : "memory")

// ===========================================================================
// NT GEMM with bias: C[M,512] = A[M,512] @ W[512,512]^T + bias  (SIMT fp32)
// k-major smem tiles (As[kk][row], pitch 72 -> conflict-free stores, LDS.128
// broadcast fragment loads): 2 LDS.128 per 16 FFMA instead of 8 scalar LDS.
// split=1: head-split [bh][n][d] with d permuted within 8-blocks
// split=2: head-split transposed [bh][d][n]
// split=0: plain row-major
// ===========================================================================
__global__ __launch_bounds__(256) void gemm_nt(
    const float* __restrict__ A, const float* __restrict__ W,
    const float* __restrict__ bias, float* __restrict__ C, int split)
{
    __shared__ float As[16][72];   // k-major: [kk][row]
    __shared__ float Ws[16][72];

    int i0 = blockIdx.y * 64;
    int j0 = blockIdx.x * 64;
    int tx = threadIdx.x, ty = threadIdx.y;
    int t  = ty * 16 + tx;
    int lr = t >> 2;          // row 0..63
    int lk = (t & 3) * 4;     // k offset 0,4,8,12

    float acc[4][4] = {};

    for (int k0 = 0; k0 < DM; k0 += 16) {
        float4 av = *(const float4*)(A + (size_t)(i0 + lr) * DM + k0 + lk);
        float4 wv = *(const float4*)(W + (size_t)(j0 + lr) * DM + k0 + lk);
        As[lk+0][lr]=av.x; As[lk+1][lr]=av.y; As[lk+2][lr]=av.z; As[lk+3][lr]=av.w;
        Ws[lk+0][lr]=wv.x; Ws[lk+1][lr]=wv.y; Ws[lk+2][lr]=wv.z; Ws[lk+3][lr]=wv.w;
        __syncthreads();
        #pragma unroll
        for (int kk = 0; kk < 16; kk++) {
            float4 a4 = *(const float4*)&As[kk][ty * 4];
            float4 w4 = *(const float4*)&Ws[kk][tx * 4];
            float a[4] = {a4.x, a4.y, a4.z, a4.w};
            float w[4] = {w4.x, w4.y, w4.z, w4.w};
            #pragma unroll
            for (int aa = 0; aa < 4; aa++)
                #pragma unroll
                for (int cc = 0; cc < 4; cc++)
                    acc[aa][cc] += a[aa] * w[cc];
        }
        __syncthreads();
    }

    int j = j0 + tx * 4;
    float4 bv = *(const float4*)(bias + j);
    #pragma unroll
    for (int aa = 0; aa < 4; aa++) {
        int i = i0 + ty * 4 + aa;
        float4 r = make_float4(acc[aa][0]+bv.x, acc[aa][1]+bv.y,
                               acc[aa][2]+bv.z, acc[aa][3]+bv.w);
        if (split == 1) {
            int b = i >> 12, il = i & (NQ-1);
            int h = j >> 6,  d  = j & (DH-1);
            int dpos = (d & ~7) | ((d >> 2) & 1);
            float* cb = C + (((size_t)(b*NH + h)*NQ + il)*DH + dpos);
            cb[0] = r.x; cb[2] = r.y; cb[4] = r.z; cb[6] = r.w;
        } else if (split == 2) {
            int b = i >> 12, il = i & (NQ-1);
            int h = j >> 6,  d  = j & (DH-1);
            float* p = C + ((size_t)(b*NH + h)*DH + d) * (size_t)NQ + il;
            p[0] = r.x; p[(size_t)NQ] = r.y;
            p[2*(size_t)NQ] = r.z; p[3*(size_t)NQ] = r.w;
        } else {
            *(float4*)(C + (size_t)i * DM + j) = r;
        }
    }
}

// ===========================================================================
// mma.sync tf32 attention (exact R7 state — best known).
// 128 threads / 4 warps (2m x 2n), 64 q-rows per CTA, 2 CTAs per SM.
// Warp tile 32q x 32n. Shuffle-free PV via k-permutation; LDS.64-paired
// fragments; P = ex2(S) with Q pre-scaled by 0.125*log2(e) and RNA tf32
// cvt on P A-frags; unnormalized P streamed to gmem; separate norm pass.
// ===========================================================================
#define PITCH 72                 // floats per smem row (288B)
#define TILEB (64*PITCH*4)       // 18432 B per tile buffer
#define KOFF(buf)  ((buf)*TILEB)
#define VOFF(buf)  (2*TILEB + (buf)*TILEB)
#define LSUM_F     (4*TILEB/4)           // float index
#define LINV_F     (LSUM_F + 128)
#define SM_BYTES   (4*TILEB + (128+64)*4)
#define NT         (NKK/64)              // 64 k-tiles
#define QSCALE     0.18033688f           // 0.125 * log2(e)
#define QROWS      64

__global__ __launch_bounds__(128, 2) void attn_mma(
    const unsigned char* __restrict__ mask, float* __restrict__ attn)
{
    extern __shared__ float smf[];
    uint32_t sb = s2u(smf);

    int tid  = threadIdx.x;
    int w    = tid >> 5, lane = tid & 31;
    int wm   = w >> 1,  wn = w & 1;
    int g    = lane >> 2, t = lane & 3;

    int bh = blockIdx.x;               // bh fastest -> K/V L2 sharing
    int b  = bh >> 3, h = bh & 7;
    int q0 = blockIdx.y * QROWS;

    const float* qg  = g_q + ((size_t)bh * NQ + q0) * DH;
    const float* kg  = g_k + (size_t)bh * NKK * DH;     // [n][d] (d permuted)
    const float* vtg = g_v + (size_t)bh * DH * NKK;     // [d][n]
    float* ab = attn + (size_t)(h * BB + b) * NQ * NKK;
    const unsigned char* mbase = mask + (size_t)b * NQ * NKK;

    // ---- stage Q (64 x 64) into smem, pre-scaled ----
    #pragma unroll
    for (int i = 0; i < 8; i++) {
        int idx = tid + i * 128;           // 1024 float4
        int r = idx >> 4, c4 = (idx & 15) << 2;
        float4 v = *(const float4*)(qg + (size_t)r * DH + c4);
        v.x *= QSCALE; v.y *= QSCALE; v.z *= QSCALE; v.w *= QSCALE;
        *(float4*)(smf + r * PITCH + c4) = v;
    }
    __syncthreads();

    // ---- preload Q A-fragments (tf32) via paired LDS.64 ----
    uint32_t qa[2][8][4];
    #pragma unroll
    for (int mb = 0; mb < 2; mb++) {
        int R = wm * 32 + mb * 16 + g;
        #pragma unroll
        for (int s = 0; s < 8; s++) {
            float2 lo = *(const float2*)(smf + R * PITCH + s * 8 + 2 * t);
            float2 hi = *(const float2*)(smf + (R + 8) * PITCH + s * 8 + 2 * t);
            qa[mb][s][0] = f2tf(lo.x);
            qa[mb][s][1] = f2tf(hi.x);
            qa[mb][s][2] = f2tf(lo.y);
            qa[mb][s][3] = f2tf(hi.y);
        }
    }
    __syncthreads();

    float oacc[2][8][4] = {};
    float lacc[2][2] = {};

    // ---- prologue: tile 0 (K rows + VT rows) ----
    #pragma unroll
    for (int i = 0; i < 8; i++) {
        int c = tid + i * 128;              // 1024 chunks of 16B per tensor
        int r = c >> 4, c16 = c & 15;
        cpa16(sb + KOFF(0) + (uint32_t)(r * PITCH + c16 * 4) * 4,
              kg + (size_t)r * DH + c16 * 4);
        cpa16(sb + VOFF(0) + (uint32_t)(r * PITCH + c16 * 4) * 4,
              vtg + (size_t)r * NKK + c16 * 4);
    }
    CP_COMMIT();

    for (int it = 0; it < NT; it++) {
        int buf = it & 1;
        CP_WAIT(0);
        __syncthreads();                    // data ready + prev buffer consumed
        if (it + 1 < NT) {
            int j0n = (it + 1) * 64, nb = buf ^ 1;
            #pragma unroll
            for (int i = 0; i < 8; i++) {
                int c = tid + i * 128;
                int r = c >> 4, c16 = c & 15;
                cpa16(sb + KOFF(nb) + (uint32_t)(r * PITCH + c16 * 4) * 4,
                      kg + (size_t)(j0n + r) * DH + c16 * 4);
                cpa16(sb + VOFF(nb) + (uint32_t)(r * PITCH + c16 * 4) * 4,
                      vtg + (size_t)r * NKK + j0n + c16 * 4);
            }
            CP_COMMIT();
        }

        const float* Ks = smf + KOFF(buf) / 4;
        const float* Vs = smf + VOFF(buf) / 4;   // [d-row][k-col]

        // ---- QK^T (paired B-frags: one LDS.64 each) ----
        float sacc[2][4][4] = {};
        #pragma unroll
        for (int s = 0; s < 8; s++) {
            #pragma unroll
            for (int j = 0; j < 4; j++) {
                int n0 = wn * 32 + j * 8;
                float2 kv = *(const float2*)(Ks + (n0 + g) * PITCH + s * 8 + 2 * t);
                uint32_t b0 = __float_as_uint(kv.x);
                uint32_t b1 = __float_as_uint(kv.y);
                mma8(sacc[0][j], qa[0][s], b0, b1);
                mma8(sacc[1][j], qa[1][s], b0, b1);
            }
        }

        // ---- epilogue + PV (shuffle-free, paired V B-frags) ----
        int jg0 = it * 64 + wn * 32;
        #pragma unroll
        for (int j = 0; j < 4; j++) {
            uint32_t pa[2][4];
            #pragma unroll
            for (int mb = 0; mb < 2; mb++) {
                int r0 = q0 + wm * 32 + mb * 16 + g;
                int colg = jg0 + j * 8 + 2 * t;
                const unsigned char* m0 = mbase + (size_t)r0 * NKK + colg;
                unsigned short mv0 = *(const unsigned short*)m0;
                unsigned short mv1 = *(const unsigned short*)(m0 + 8 * NKK);
                float* s4 = sacc[mb][j];
                float p0 = (mv0 & 0xff) ? 0.f : ex2f(s4[0]);
                float p1 = (mv0 >> 8)   ? 0.f : ex2f(s4[1]);
                float p2 = (mv1 & 0xff) ? 0.f : ex2f(s4[2]);
                float p3 = (mv1 >> 8)   ? 0.f : ex2f(s4[3]);
                lacc[mb][0] += p0 + p1;
                lacc[mb][1] += p2 + p3;
                __stcs((float2*)(ab + (size_t)r0 * NKK + colg), make_float2(p0, p1));
                __stcs((float2*)(ab + (size_t)(r0 + 8) * NKK + colg), make_float2(p2, p3));
                pa[mb][0] = f2tf(p0);
                pa[mb][1] = f2tf(p2);
                pa[mb][2] = f2tf(p1);
                pa[mb][3] = f2tf(p3);
            }
            int k0 = wn * 32 + j * 8;
            #pragma unroll
            for (int jd = 0; jd < 8; jd++) {
                float2 vv = *(const float2*)(Vs + (jd * 8 + g) * PITCH + k0 + 2 * t);
                uint32_t b0 = __float_as_uint(vv.x);
                uint32_t b1 = __float_as_uint(vv.y);
                mma8(oacc[0][jd], pa[0], b0, b1);
                mma8(oacc[1][jd], pa[1], b0, b1);
            }
        }
    }

    // ---- rowsum reduce ----
    #pragma unroll
    for (int off = 1; off <= 2; off <<= 1) {
        #pragma unroll
        for (int mb = 0; mb < 2; mb++) {
            lacc[mb][0] += __shfl_xor_sync(0xffffffffu, lacc[mb][0], off);
            lacc[mb][1] += __shfl_xor_sync(0xffffffffu, lacc[mb][1], off);
        }
    }
    float* lsum = smf + LSUM_F;
    float* linv = smf + LINV_F;
    __syncthreads();
    if (t == 0) {
        #pragma unroll
        for (int mb = 0; mb < 2; mb++) {
            lsum[wn * 64 + wm * 32 + mb * 16 + g]     = lacc[mb][0];
            lsum[wn * 64 + wm * 32 + mb * 16 + g + 8] = lacc[mb][1];
        }
    }
    __syncthreads();
    if (tid < QROWS) {
        float tot = lsum[tid] + lsum[64 + tid];
        g_l[(size_t)bh * NQ + q0 + tid] = tot;
        linv[tid] = 1.0f / tot;
    }
    __syncthreads();

    // ---- cross-warp(n) O reduction via smem (reuse KV region) ----
    if (wn == 1) {
        #pragma unroll
        for (int mb = 0; mb < 2; mb++) {
            int r = wm * 32 + mb * 16 + g;
            #pragma unroll
            for (int jd = 0; jd < 8; jd++) {
                *(float2*)(smf + r * PITCH + jd * 8 + 2 * t) =
                    make_float2(oacc[mb][jd][0], oacc[mb][jd][1]);
                *(float2*)(smf + (r + 8) * PITCH + jd * 8 + 2 * t) =
                    make_float2(oacc[mb][jd][2], oacc[mb][jd][3]);
            }
        }
    }
    __syncthreads();
    if (wn == 0) {
        #pragma unroll
        for (int mb = 0; mb < 2; mb++) {
            int r = wm * 32 + mb * 16 + g;
            float i0v = linv[r], i1v = linv[r + 8];
            float* og0 = g_o + (size_t)(b * NQ + q0 + r) * DM + h * DH;
            float* og1 = og0 + 8 * DM;
            #pragma unroll
            for (int jd = 0; jd < 8; jd++) {
                float2 e0 = *(float2*)(smf + r * PITCH + jd * 8 + 2 * t);
                float2 e1 = *(float2*)(smf + (r + 8) * PITCH + jd * 8 + 2 * t);
                *(float2*)(og0 + jd * 8 + 2 * t) = make_float2(
                    (oacc[mb][jd][0] + e0.x) * i0v, (oacc[mb][jd][1] + e0.y) * i0v);
                *(float2*)(og1 + jd * 8 + 2 * t) = make_float2(
                    (oacc[mb][jd][2] + e1.x) * i1v, (oacc[mb][jd][3] + e1.y) * i1v);
            }
        }
    }
}

// ===========================================================================
// Streaming normalize: attn[h,b,i,:] /= l[b,h,i]
// ===========================================================================
__global__ __launch_bounds__(256) void norm_attn(float* __restrict__ attn)
{
    size_t idx = (size_t)blockIdx.x * blockDim.x + threadIdx.x;
    size_t rowi = idx >> 10;
    int i  = (int)(rowi & (NQ - 1));
    int hb = (int)(rowi >> 12);
    int h = hb >> 1, b = hb & 1;
    float inv = 1.0f / g_l[(size_t)(b * NH + h) * NQ + i];
    float4 v = __ldcs((const float4*)attn + idx);
    v.x *= inv; v.y *= inv; v.z *= inv; v.w *= inv;
    __stcs((float4*)attn + idx, v);
}

extern "C" void kernel_launch(void* const* d_in, const int* in_sizes, int n_in,
                              void* d_out, int out_size)
{
    const float* q  = (const float*)d_in[0];
    const float* k  = (const float*)d_in[1];
    const float* v  = (const float*)d_in[2];
    const unsigned char* mask = (const unsigned char*)d_in[3];
    const float* Wq = (const float*)d_in[4];
    const float* bq = (const float*)d_in[5];
    const float* Wk = (const float*)d_in[6];
    const float* bk = (const float*)d_in[7];
    const float* Wv = (const float*)d_in[8];
    const float* bv = (const float*)d_in[9];
    const float* Wo = (const float*)d_in[10];
    const float* bo = (const float*)d_in[11];

    float* outbuf = (float*)d_out;
    float* attn = outbuf;
    float* outp = outbuf + ATTN_ELEMS;

    float *gq, *gk, *gv, *go;
    cudaGetSymbolAddress((void**)&gq, g_q);
    cudaGetSymbolAddress((void**)&gk, g_k);
    cudaGetSymbolAddress((void**)&gv, g_v);
    cudaGetSymbolAddress((void**)&go, g_o);

    dim3 blk(16, 16);
    dim3 gproj(DM / 64, MROWS / 64);

    gemm_nt<<<gproj, blk>>>(q, Wq, bq, gq, 1);
    gemm_nt<<<gproj, blk>>>(k, Wk, bk, gk, 1);
    gemm_nt<<<gproj, blk>>>(v, Wv, bv, gv, 2);   // transposed per head

    cudaFuncSetAttribute(attn_mma,
        cudaFuncAttributeMaxDynamicSharedMemorySize, SM_BYTES);
    attn_mma<<<dim3(BB * NH, NQ / QROWS), 128, SM_BYTES>>>(mask, attn);

    norm_attn<<<(unsigned)(ATTN_ELEMS / 4 / 256), 256>>>(attn);

    gemm_nt<<<gproj, blk>>>(go, Wo, bo, outp, 0);
}